// round 13
// baseline (speedup 1.0000x reference)
#include <cuda_runtime.h>
#include <cstdint>

#define N_NODES    100000
#define EMB_DIM    128
#define BATCH      16384
#define NUM_SAMPLE 25

#define VEC_PER_ROW (EMB_DIM / 4)   // 32 float4 per row

// One CTA == one warp == one row (R12-proven best grain).
#define BLOCK_THREADS 32
#define GRID_BLOCKS   BATCH   // 16384

__global__ __launch_bounds__(BLOCK_THREADS) void mean_agg_kernel(
    const float4* __restrict__ emb,      // [N_NODES, 32] as float4
    const int* __restrict__ neigh,       // [BATCH, NUM_SAMPLE], int32
    float4* __restrict__ out)            // [BATCH, 32] as float4
{
    const int row  = blockIdx.x;
    const int lane = threadIdx.x;        // 0..31

    // Lane l (< 25) holds sample l's neighbor index for this row.
    // __ldcs: indices are read exactly once -> evict-first, don't pollute L2.
    const int* nb = neigh + row * NUM_SAMPLE;
    int my_idx = (lane < NUM_SAMPLE) ? __ldcs(&nb[lane]) : 0;

    float4 acc = make_float4(0.f, 0.f, 0.f, 0.f);

    #pragma unroll
    for (int s = 0; s < NUM_SAMPLE; ++s) {
        int id = __shfl_sync(0xffffffffu, my_idx, s);
        // __ldcg: cache in L2 (table is hot there) but skip L1 (zero L1 reuse
        // with random indices).
        float4 v = __ldcg(&emb[(unsigned)id * VEC_PER_ROW + lane]);
        acc.x += v.x;
        acc.y += v.y;
        acc.z += v.z;
        acc.w += v.w;
    }

    const float inv = 1.0f / (float)NUM_SAMPLE;   // 0.04
    acc.x *= inv; acc.y *= inv; acc.z *= inv; acc.w *= inv;

    // __stcs: streaming store, evict-first -> output writeback doesn't evict
    // live embedding-table lines from L2.
    __stcs(&out[(unsigned)row * VEC_PER_ROW + lane], acc);
}

extern "C" void kernel_launch(void* const* d_in, const int* in_sizes, int n_in,
                              void* d_out, int out_size)
{
    const float4* emb   = (const float4*)d_in[0];
    const int*    neigh = (const int*)d_in[1];
    float4*       out   = (float4*)d_out;

    mean_agg_kernel<<<GRID_BLOCKS, BLOCK_THREADS>>>(emb, neigh, out);
}

// round 14
// speedup vs baseline: 1.0019x; 1.0019x over previous
#include <cuda_runtime.h>
#include <cstdint>

#define N_NODES    100000
#define EMB_DIM    128
#define BATCH      16384
#define NUM_SAMPLE 25

#define VEC_PER_ROW (EMB_DIM / 4)   // 32 float4 per row

// Final kernel (R12): one CTA == one warp == one row. Finest scheduling grain;
// ptxas uses 64 regs/thread -> maximal per-warp gather MLP. Default __ldg
// caching (L1 enabled) measured fastest; all hint/layout/precision variants
// empirically regressed.
#define BLOCK_THREADS 32
#define GRID_BLOCKS   BATCH   // 16384

__global__ __launch_bounds__(BLOCK_THREADS) void mean_agg_kernel(
    const float4* __restrict__ emb,      // [N_NODES, 32] as float4
    const int* __restrict__ neigh,       // [BATCH, NUM_SAMPLE], int32
    float4* __restrict__ out)            // [BATCH, 32] as float4
{
    const int row  = blockIdx.x;
    const int lane = threadIdx.x;        // 0..31

    // Lane l (< 25) holds sample l's neighbor index for this row.
    const int* nb = neigh + row * NUM_SAMPLE;
    int my_idx = (lane < NUM_SAMPLE) ? nb[lane] : 0;

    float4 acc = make_float4(0.f, 0.f, 0.f, 0.f);

    #pragma unroll
    for (int s = 0; s < NUM_SAMPLE; ++s) {
        int id = __shfl_sync(0xffffffffu, my_idx, s);
        float4 v = __ldg(&emb[(unsigned)id * VEC_PER_ROW + lane]);
        acc.x += v.x;
        acc.y += v.y;
        acc.z += v.z;
        acc.w += v.w;
    }

    const float inv = 1.0f / (float)NUM_SAMPLE;   // 0.04
    acc.x *= inv; acc.y *= inv; acc.z *= inv; acc.w *= inv;

    out[(unsigned)row * VEC_PER_ROW + lane] = acc;
}

extern "C" void kernel_launch(void* const* d_in, const int* in_sizes, int n_in,
                              void* d_out, int out_size)
{
    const float4* emb   = (const float4*)d_in[0];
    const int*    neigh = (const int*)d_in[1];
    float4*       out   = (float4*)d_out;

    mean_agg_kernel<<<GRID_BLOCKS, BLOCK_THREADS>>>(emb, neigh, out);
}